// round 1
// baseline (speedup 1.0000x reference)
#include <cuda_runtime.h>
#include <math.h>

#define NN 4096
#define PP 128
#define LL 32

// ---------------- scratch (device globals; no allocation) ----------------
__device__ float g_x2[NN];
__device__ float g_d2[(size_t)NN * NN];   // clamped squared distances (64 MB)
__device__ int   g_mdbits;                // atomicMax of d2c as ordered int
__device__ float g_mu[NN * PP];
__device__ float g_U[NN * PP];
__device__ float g_un2[NN];
__device__ float g_yU[NN];
__device__ float g_eZ[NN * PP];

// ---------------- tiny init ----------------
__global__ void k_zero(float* out) {
    g_mdbits = 0;
    out[0] = 0.0f;
}

// ---------------- x2[i] = ||x_i||^2 ----------------
__global__ void k_x2(const float* __restrict__ x) {
    int row  = blockIdx.x;
    int lane = threadIdx.x;              // 32 threads
    const float4* x4 = (const float4*)x;
    float4 v = x4[row * 32 + lane];
    float s = v.x * v.x + v.y * v.y + v.z * v.z + v.w * v.w;
    #pragma unroll
    for (int o = 16; o; o >>= 1) s += __shfl_xor_sync(0xffffffffu, s, o);
    if (lane == 0) g_x2[row] = s;
}

// ---------------- Gram / dist^2 (64x64 tile, 4x4 per thread) ----------------
__global__ void k_gram(const float* __restrict__ x) {
    __shared__ float As[16][64];
    __shared__ float Bs[16][64];
    int jb = blockIdx.x * 64, ib = blockIdx.y * 64;
    int t  = threadIdx.x;
    int tx = t & 15, ty = t >> 4;
    float acc[4][4];
    #pragma unroll
    for (int a = 0; a < 4; a++)
        #pragma unroll
        for (int b = 0; b < 4; b++) acc[a][b] = 0.0f;

    int lr = t >> 2, lk = (t & 3) * 4;
    for (int k0 = 0; k0 < PP; k0 += 16) {
        float4 av = *(const float4*)(x + (size_t)(ib + lr) * PP + k0 + lk);
        float4 bv = *(const float4*)(x + (size_t)(jb + lr) * PP + k0 + lk);
        As[lk + 0][lr] = av.x; As[lk + 1][lr] = av.y;
        As[lk + 2][lr] = av.z; As[lk + 3][lr] = av.w;
        Bs[lk + 0][lr] = bv.x; Bs[lk + 1][lr] = bv.y;
        Bs[lk + 2][lr] = bv.z; Bs[lk + 3][lr] = bv.w;
        __syncthreads();
        #pragma unroll
        for (int kk = 0; kk < 16; kk++) {
            float4 a4 = *(const float4*)&As[kk][ty * 4];
            float4 b4 = *(const float4*)&Bs[kk][tx * 4];
            float ar[4] = {a4.x, a4.y, a4.z, a4.w};
            float br[4] = {b4.x, b4.y, b4.z, b4.w};
            #pragma unroll
            for (int a = 0; a < 4; a++)
                #pragma unroll
                for (int b = 0; b < 4; b++)
                    acc[a][b] = fmaf(ar[a], br[b], acc[a][b]);
        }
        __syncthreads();
    }

    float lmax = 0.0f;
    #pragma unroll
    for (int a = 0; a < 4; a++) {
        int i = ib + ty * 4 + a;
        float xi2 = g_x2[i];
        float4 o;
        float* op = &o.x;
        #pragma unroll
        for (int b = 0; b < 4; b++) {
            int j = jb + tx * 4 + b;
            float d2 = xi2 + g_x2[j] - 2.0f * acc[a][b];
            d2 = fmaxf(d2, 1e-12f);
            op[b] = d2;
            lmax = fmaxf(lmax, d2);
        }
        *(float4*)(g_d2 + (size_t)i * NN + jb + tx * 4) = o;
    }
    #pragma unroll
    for (int o = 16; o; o >>= 1)
        lmax = fmaxf(lmax, __shfl_xor_sync(0xffffffffu, lmax, o));
    if ((t & 31) == 0) atomicMax(&g_mdbits, __float_as_int(lmax));
}

// ---------------- alpha pass: mu[j] = sum_i w1(d)*x_i / sum_i w1 ----------------
// 32 query columns per block; i-loop in tiles of 64.
__global__ void k_alpha(const float* __restrict__ x, const float* __restrict__ r0p) {
    extern __shared__ float sm[];
    float* Xi  = sm;                 // 64*128
    float* ws  = Xi + 64 * PP;       // 64*33
    float* red = ws + 64 * 33;       // 8*32
    int jb = blockIdx.x * 32;
    int t  = threadIdx.x;
    int jj = t & 31, grp = t >> 5;

    float md     = sqrtf(__int_as_float(g_mdbits));
    float r0e    = fminf(__ldg(r0p), md);
    float rr     = r0e * r0e;
    float inv_rr = 1.0f / rr;

    float acc[16];
    #pragma unroll
    for (int q = 0; q < 16; q++) acc[q] = 0.0f;
    float sa = 0.0f;

    const float4* x4g = (const float4*)x;
    for (int ib = 0; ib < NN; ib += 64) {
        #pragma unroll
        for (int u = 0; u < 8; u++) {
            int idx = t + u * 256;
            ((float4*)Xi)[idx] = x4g[ib * 32 + idx];
        }
        #pragma unroll
        for (int s = 0; s < 8; s++) {
            int il = grp * 8 + s;
            float d2c = g_d2[(size_t)(ib + il) * NN + jb + jj];
            float w = 0.0f;
            if (d2c < rr) { float b = 1.0f - d2c * inv_rr; w = b * b * b; }
            ws[il * 33 + jj] = w;
            sa += w;
        }
        __syncthreads();
        const float4* Xi4 = (const float4*)Xi;
        #pragma unroll 4
        for (int i = 0; i < 64; i++) {
            float w   = ws[i * 33 + jj];
            float4 v0 = Xi4[i * 32 + grp * 4 + 0];
            float4 v1 = Xi4[i * 32 + grp * 4 + 1];
            float4 v2 = Xi4[i * 32 + grp * 4 + 2];
            float4 v3 = Xi4[i * 32 + grp * 4 + 3];
            acc[0]  = fmaf(w, v0.x, acc[0]);  acc[1]  = fmaf(w, v0.y, acc[1]);
            acc[2]  = fmaf(w, v0.z, acc[2]);  acc[3]  = fmaf(w, v0.w, acc[3]);
            acc[4]  = fmaf(w, v1.x, acc[4]);  acc[5]  = fmaf(w, v1.y, acc[5]);
            acc[6]  = fmaf(w, v1.z, acc[6]);  acc[7]  = fmaf(w, v1.w, acc[7]);
            acc[8]  = fmaf(w, v2.x, acc[8]);  acc[9]  = fmaf(w, v2.y, acc[9]);
            acc[10] = fmaf(w, v2.z, acc[10]); acc[11] = fmaf(w, v2.w, acc[11]);
            acc[12] = fmaf(w, v3.x, acc[12]); acc[13] = fmaf(w, v3.y, acc[13]);
            acc[14] = fmaf(w, v3.z, acc[14]); acc[15] = fmaf(w, v3.w, acc[15]);
        }
        __syncthreads();
    }

    red[grp * 32 + jj] = sa;
    __syncthreads();
    if (t < 32) {
        float s2 = 0.0f;
        #pragma unroll
        for (int g = 0; g < 8; g++) s2 += red[g * 32 + t];
        red[t] = s2;
    }
    __syncthreads();
    float s2  = red[jj];
    int   j   = jb + jj;
    float inv = (s2 > 0.0f) ? 1.0f / s2 : 0.0f;
    #pragma unroll
    for (int q = 0; q < 16; q++) {
        int p = grp * 16 + q;
        float v = acc[q] * inv;
        if (s2 == 0.0f) v = x[(size_t)j * PP + p];   // NaN-guard fallback to y
        g_mu[(size_t)j * PP + p] = v;
    }
}

// ---------------- U = x - mu, ||U||^2, <y,U> ----------------
__global__ void k_U(const float* __restrict__ x) {
    int row = blockIdx.x;
    int p   = threadIdx.x;  // 128
    float xv = x[(size_t)row * PP + p];
    float m  = g_mu[(size_t)row * PP + p];
    float u  = xv - m;
    g_U[(size_t)row * PP + p] = u;
    float a = u * u, b = xv * u;
    #pragma unroll
    for (int o = 16; o; o >>= 1) {
        a += __shfl_xor_sync(0xffffffffu, a, o);
        b += __shfl_xor_sync(0xffffffffu, b, o);
    }
    __shared__ float ra[4], rb[4];
    if ((p & 31) == 0) { ra[p >> 5] = a; rb[p >> 5] = b; }
    __syncthreads();
    if (p == 0) {
        g_un2[row] = ra[0] + ra[1] + ra[2] + ra[3];
        g_yU[row]  = rb[0] + rb[1] + rb[2] + rb[3];
    }
}

// ---------------- weight2 ----------------
__device__ __forceinline__ float wfun2(float d, float r) {
    if (d < 0.5f * r) return 1.0f;
    if (d >= r) return 0.0f;
    float tq = (2.0f * d - r) / r;
    float b  = 1.0f - tq * tq;
    return b * b * b;
}

// ---------------- beta pass ----------------
__global__ void k_beta(const float* __restrict__ x,
                       const float* __restrict__ r1p,
                       const float* __restrict__ r2p) {
    extern __shared__ float sm[];
    float* Us  = sm;                   // 32*132 (padded rows for conflict-free LDS.128)
    float* Xi  = Us + 32 * 132;        // 64*128
    float* ws  = Xi + 64 * PP;         // 64*33
    float* red = ws + 64 * 33;         // 8*32
    int jb = blockIdx.x * 32;
    int t  = threadIdx.x;
    int jj = t & 31, grp = t >> 5;

    float md  = sqrtf(__int_as_float(g_mdbits));
    float r1e = fminf(__ldg(r1p), md);
    float r2e = fminf(__ldg(r2p), md);

    #pragma unroll
    for (int u = 0; u < 16; u++) {
        int idx = t + u * 256;                   // 0..4095
        int r = idx >> 7, c = idx & 127;
        Us[r * 132 + c] = g_U[(size_t)(jb + r) * PP + c];
    }
    __syncthreads();

    float un2 = g_un2[jb + jj];
    float yu  = g_yU[jb + jj];

    float acc[16];
    #pragma unroll
    for (int q = 0; q < 16; q++) acc[q] = 0.0f;
    float sb = 0.0f;

    const float4* x4g = (const float4*)x;
    const float4* Uv  = (const float4*)(Us + jj * 132);

    for (int ib = 0; ib < NN; ib += 64) {
        #pragma unroll
        for (int u = 0; u < 8; u++) {
            int idx = t + u * 256;
            ((float4*)Xi)[idx] = x4g[ib * 32 + idx];
        }
        __syncthreads();
        const float4* Xi4 = (const float4*)Xi;

        // ps[i][jj] = <x_i, U_jj>
        float ps[8];
        #pragma unroll
        for (int s = 0; s < 8; s++) ps[s] = 0.0f;
        #pragma unroll 4
        for (int k4 = 0; k4 < 32; k4++) {
            float4 u4 = Uv[k4];
            #pragma unroll
            for (int s = 0; s < 8; s++) {
                float4 xv = Xi4[(grp * 8 + s) * 32 + k4];
                ps[s] = fmaf(xv.x, u4.x, fmaf(xv.y, u4.y,
                        fmaf(xv.z, u4.z, fmaf(xv.w, u4.w, ps[s]))));
            }
        }
        // weights
        #pragma unroll
        for (int s = 0; s < 8; s++) {
            int il = grp * 8 + s;
            float d2c = g_d2[(size_t)(ib + il) * NN + jb + jj];
            float psv = ps[s] - yu;
            float du2 = fmaxf(psv * psv * un2, 1e-6f);
            float dv  = sqrtf(fmaxf(d2c - du2, 1e-6f));
            float du  = sqrtf(du2);
            float w   = wfun2(dv, r1e) * wfun2(du, r2e);
            ws[il * 33 + jj] = w;
            sb += w;
        }
        __syncthreads();
        // accumulate eZ
        #pragma unroll 4
        for (int i = 0; i < 64; i++) {
            float w   = ws[i * 33 + jj];
            float4 v0 = Xi4[i * 32 + grp * 4 + 0];
            float4 v1 = Xi4[i * 32 + grp * 4 + 1];
            float4 v2 = Xi4[i * 32 + grp * 4 + 2];
            float4 v3 = Xi4[i * 32 + grp * 4 + 3];
            acc[0]  = fmaf(w, v0.x, acc[0]);  acc[1]  = fmaf(w, v0.y, acc[1]);
            acc[2]  = fmaf(w, v0.z, acc[2]);  acc[3]  = fmaf(w, v0.w, acc[3]);
            acc[4]  = fmaf(w, v1.x, acc[4]);  acc[5]  = fmaf(w, v1.y, acc[5]);
            acc[6]  = fmaf(w, v1.z, acc[6]);  acc[7]  = fmaf(w, v1.w, acc[7]);
            acc[8]  = fmaf(w, v2.x, acc[8]);  acc[9]  = fmaf(w, v2.y, acc[9]);
            acc[10] = fmaf(w, v2.z, acc[10]); acc[11] = fmaf(w, v2.w, acc[11]);
            acc[12] = fmaf(w, v3.x, acc[12]); acc[13] = fmaf(w, v3.y, acc[13]);
            acc[14] = fmaf(w, v3.z, acc[14]); acc[15] = fmaf(w, v3.w, acc[15]);
        }
        __syncthreads();
    }

    red[grp * 32 + jj] = sb;
    __syncthreads();
    if (t < 32) {
        float s2 = 0.0f;
        #pragma unroll
        for (int g = 0; g < 8; g++) s2 += red[g * 32 + t];
        red[t] = s2;
    }
    __syncthreads();
    float s2  = red[jj];
    int   j   = jb + jj;
    float inv = (s2 > 0.0f) ? 1.0f / s2 : 0.0f;
    #pragma unroll
    for (int q = 0; q < 16; q++) {
        int p = grp * 16 + q;
        float v = acc[q] * inv;
        if (s2 == 0.0f) v = x[(size_t)j * PP + p];
        g_eZ[(size_t)j * PP + p] = v;
    }
}

// ---------------- fused MLP + MSE loss ----------------
__device__ __forceinline__ float gelu_exact(float v) {
    return 0.5f * v * (1.0f + erff(v * 0.70710678118654752f));
}

__global__ void k_mlp(const float* __restrict__ x,
                      const float* __restrict__ We1, const float* __restrict__ be1,
                      const float* __restrict__ We2, const float* __restrict__ be2,
                      const float* __restrict__ Wd1, const float* __restrict__ bd1,
                      const float* __restrict__ Wd2, const float* __restrict__ bd2,
                      float* __restrict__ out) {
    __shared__ float We1s[32 * 129];
    __shared__ float Wd2s[128 * 33];
    __shared__ float We2s[32 * 33];
    __shared__ float Wd1s[32 * 33];
    __shared__ float be1s[32], be2s[32], bd1s[32], bd2s[128];
    int t = threadIdx.x;
    for (int idx = t; idx < 32 * 128; idx += 256)
        We1s[(idx >> 7) * 129 + (idx & 127)] = We1[idx];
    for (int idx = t; idx < 128 * 32; idx += 256)
        Wd2s[(idx >> 5) * 33 + (idx & 31)] = Wd2[idx];
    for (int idx = t; idx < 32 * 32; idx += 256) {
        We2s[(idx >> 5) * 33 + (idx & 31)] = We2[idx];
        Wd1s[(idx >> 5) * 33 + (idx & 31)] = Wd1[idx];
    }
    if (t < 32) { be1s[t] = be1[t]; be2s[t] = be2[t]; bd1s[t] = bd1[t]; }
    if (t < 128) bd2s[t] = bd2[t];
    __syncthreads();

    int lane = t & 31;
    int warp = t >> 5;
    int gw = blockIdx.x * 8 + warp;
    int nw = gridDim.x * 8;
    float part = 0.0f;

    for (int row = gw; row < NN; row += nw) {
        const float* yrow = g_eZ + (size_t)row * PP;
        float y0 = yrow[lane], y1 = yrow[32 + lane];
        float y2 = yrow[64 + lane], y3 = yrow[96 + lane];

        float h = be1s[lane];
        const float* wrow = We1s + lane * 129;
        #pragma unroll 8
        for (int k = 0; k < 32; k++) {
            h = fmaf(__shfl_sync(0xffffffffu, y0, k), wrow[k], h);
            h = fmaf(__shfl_sync(0xffffffffu, y1, k), wrow[32 + k], h);
            h = fmaf(__shfl_sync(0xffffffffu, y2, k), wrow[64 + k], h);
            h = fmaf(__shfl_sync(0xffffffffu, y3, k), wrow[96 + k], h);
        }
        h = gelu_exact(h);

        float z = be2s[lane];
        const float* w2row = We2s + lane * 33;
        #pragma unroll
        for (int m = 0; m < 32; m++)
            z = fmaf(__shfl_sync(0xffffffffu, h, m), w2row[m], z);

        float h2 = bd1s[lane];
        const float* w3row = Wd1s + lane * 33;
        #pragma unroll
        for (int m = 0; m < 32; m++)
            h2 = fmaf(__shfl_sync(0xffffffffu, z, m), w3row[m], h2);
        h2 = gelu_exact(h2);

        float xh[4];
        #pragma unroll
        for (int q = 0; q < 4; q++) xh[q] = bd2s[q * 32 + lane];
        #pragma unroll
        for (int m = 0; m < 32; m++) {
            float hm = __shfl_sync(0xffffffffu, h2, m);
            #pragma unroll
            for (int q = 0; q < 4; q++)
                xh[q] = fmaf(hm, Wd2s[(q * 32 + lane) * 33 + m], xh[q]);
        }
        #pragma unroll
        for (int q = 0; q < 4; q++) {
            int p = q * 32 + lane;
            float s   = 1.0f / (1.0f + expf(-xh[q]));
            float dlt = x[(size_t)row * PP + p] - s;
            part = fmaf(dlt, dlt, part);
        }
    }
    #pragma unroll
    for (int o = 16; o; o >>= 1) part += __shfl_xor_sync(0xffffffffu, part, o);
    if (lane == 0) atomicAdd(out, part * (1.0f / ((float)NN * (float)PP)));
}

// ---------------- launch ----------------
extern "C" void kernel_launch(void* const* d_in, const int* in_sizes, int n_in,
                              void* d_out, int out_size) {
    const float* x   = (const float*)d_in[0];
    const float* r0  = (const float*)d_in[1];
    const float* r1  = (const float*)d_in[2];
    const float* r2  = (const float*)d_in[3];
    const float* We1 = (const float*)d_in[4];
    const float* be1 = (const float*)d_in[5];
    const float* We2 = (const float*)d_in[6];
    const float* be2 = (const float*)d_in[7];
    const float* Wd1 = (const float*)d_in[8];
    const float* bd1 = (const float*)d_in[9];
    const float* Wd2 = (const float*)d_in[10];
    const float* bd2 = (const float*)d_in[11];
    float* out = (float*)d_out;

    size_t smA = (size_t)(64 * PP + 64 * 33 + 8 * 32) * sizeof(float);            // 42240
    size_t smB = (size_t)(32 * 132 + 64 * PP + 64 * 33 + 8 * 32) * sizeof(float); // 59136
    cudaFuncSetAttribute(k_alpha, cudaFuncAttributeMaxDynamicSharedMemorySize, (int)smA);
    cudaFuncSetAttribute(k_beta,  cudaFuncAttributeMaxDynamicSharedMemorySize, (int)smB);

    k_zero<<<1, 1>>>(out);
    k_x2<<<NN, 32>>>(x);
    k_gram<<<dim3(64, 64), 256>>>(x);
    k_alpha<<<128, 256, smA>>>(x, r0);
    k_U<<<NN, 128>>>(x);
    k_beta<<<128, 256, smB>>>(x, r1, r2);
    k_mlp<<<64, 256>>>(x, We1, be1, We2, be2, Wd1, bd1, Wd2, bd2, out);
}

// round 2
// speedup vs baseline: 1.1696x; 1.1696x over previous
#include <cuda_runtime.h>
#include <math.h>

#define NN 4096
#define PP 128
#define LL 32
#define SPLIT 4
#define CHUNK (NN / SPLIT)   // 1024 i's per split

// ---------------- scratch (device globals; no allocation) ----------------
__device__ float g_x2[NN];
__device__ float g_d2[(size_t)NN * NN];   // clamped squared distances (64 MB)
__device__ int   g_mdbits;                // atomicMax of d2c as ordered int
__device__ float g_muP[SPLIT * NN * PP];  // unnormalized mu partials (8 MB)
__device__ float g_saP[SPLIT * NN];       // alpha weight-sum partials
__device__ float g_eZP[SPLIT * NN * PP];  // unnormalized eZ partials (8 MB)
__device__ float g_sbP[SPLIT * NN];       // beta weight-sum partials
__device__ float g_U[NN * PP];
__device__ float g_un2[NN];
__device__ float g_yU[NN];

// ---------------- tiny init ----------------
__global__ void k_zero(float* out) {
    g_mdbits = 0;
    out[0] = 0.0f;
}

// ---------------- x2[i] = ||x_i||^2 ----------------
__global__ void k_x2(const float* __restrict__ x) {
    int row  = blockIdx.x;
    int lane = threadIdx.x;              // 32 threads
    const float4* x4 = (const float4*)x;
    float4 v = x4[row * 32 + lane];
    float s = v.x * v.x + v.y * v.y + v.z * v.z + v.w * v.w;
    #pragma unroll
    for (int o = 16; o; o >>= 1) s += __shfl_xor_sync(0xffffffffu, s, o);
    if (lane == 0) g_x2[row] = s;
}

// ---------------- Gram / dist^2 (64x64 tile, 4x4 per thread) ----------------
__global__ void k_gram(const float* __restrict__ x) {
    __shared__ float As[16][64];
    __shared__ float Bs[16][64];
    int jb = blockIdx.x * 64, ib = blockIdx.y * 64;
    int t  = threadIdx.x;
    int tx = t & 15, ty = t >> 4;
    float acc[4][4];
    #pragma unroll
    for (int a = 0; a < 4; a++)
        #pragma unroll
        for (int b = 0; b < 4; b++) acc[a][b] = 0.0f;

    int lr = t >> 2, lk = (t & 3) * 4;
    for (int k0 = 0; k0 < PP; k0 += 16) {
        float4 av = *(const float4*)(x + (size_t)(ib + lr) * PP + k0 + lk);
        float4 bv = *(const float4*)(x + (size_t)(jb + lr) * PP + k0 + lk);
        As[lk + 0][lr] = av.x; As[lk + 1][lr] = av.y;
        As[lk + 2][lr] = av.z; As[lk + 3][lr] = av.w;
        Bs[lk + 0][lr] = bv.x; Bs[lk + 1][lr] = bv.y;
        Bs[lk + 2][lr] = bv.z; Bs[lk + 3][lr] = bv.w;
        __syncthreads();
        #pragma unroll
        for (int kk = 0; kk < 16; kk++) {
            float4 a4 = *(const float4*)&As[kk][ty * 4];
            float4 b4 = *(const float4*)&Bs[kk][tx * 4];
            float ar[4] = {a4.x, a4.y, a4.z, a4.w};
            float br[4] = {b4.x, b4.y, b4.z, b4.w};
            #pragma unroll
            for (int a = 0; a < 4; a++)
                #pragma unroll
                for (int b = 0; b < 4; b++)
                    acc[a][b] = fmaf(ar[a], br[b], acc[a][b]);
        }
        __syncthreads();
    }

    float lmax = 0.0f;
    #pragma unroll
    for (int a = 0; a < 4; a++) {
        int i = ib + ty * 4 + a;
        float xi2 = g_x2[i];
        float4 o;
        float* op = &o.x;
        #pragma unroll
        for (int b = 0; b < 4; b++) {
            int j = jb + tx * 4 + b;
            float d2 = xi2 + g_x2[j] - 2.0f * acc[a][b];
            d2 = fmaxf(d2, 1e-12f);
            op[b] = d2;
            lmax = fmaxf(lmax, d2);
        }
        *(float4*)(g_d2 + (size_t)i * NN + jb + tx * 4) = o;
    }
    #pragma unroll
    for (int o = 16; o; o >>= 1)
        lmax = fmaxf(lmax, __shfl_xor_sync(0xffffffffu, lmax, o));
    if ((t & 31) == 0) atomicMax(&g_mdbits, __float_as_int(lmax));
}

// ---------------- alpha pass (partial over i-range) ----------------
// 32 query columns per block; i-loop over this split's CHUNK in tiles of 64.
__global__ void k_alpha(const float* __restrict__ x, const float* __restrict__ r0p) {
    extern __shared__ float sm[];
    float* Xi  = sm;                 // 64*128
    float* ws  = Xi + 64 * PP;       // 64*33
    float* red = ws + 64 * 33;       // 8*32
    int jb  = blockIdx.x * 32;
    int sid = blockIdx.y;
    int t   = threadIdx.x;
    int jj = t & 31, grp = t >> 5;

    float md     = sqrtf(__int_as_float(g_mdbits));
    float r0e    = fminf(__ldg(r0p), md);
    float rr     = r0e * r0e;
    float inv_rr = 1.0f / rr;

    float acc[16];
    #pragma unroll
    for (int q = 0; q < 16; q++) acc[q] = 0.0f;
    float sa = 0.0f;

    const float4* x4g = (const float4*)x;
    int ibeg = sid * CHUNK, iend = ibeg + CHUNK;
    for (int ib = ibeg; ib < iend; ib += 64) {
        #pragma unroll
        for (int u = 0; u < 8; u++) {
            int idx = t + u * 256;
            ((float4*)Xi)[idx] = x4g[ib * 32 + idx];
        }
        #pragma unroll
        for (int s = 0; s < 8; s++) {
            int il = grp * 8 + s;
            float d2c = g_d2[(size_t)(ib + il) * NN + jb + jj];
            float w = 0.0f;
            if (d2c < rr) { float b = 1.0f - d2c * inv_rr; w = b * b * b; }
            ws[il * 33 + jj] = w;
            sa += w;
        }
        __syncthreads();
        const float4* Xi4 = (const float4*)Xi;
        #pragma unroll 4
        for (int i = 0; i < 64; i++) {
            float w   = ws[i * 33 + jj];
            float4 v0 = Xi4[i * 32 + grp * 4 + 0];
            float4 v1 = Xi4[i * 32 + grp * 4 + 1];
            float4 v2 = Xi4[i * 32 + grp * 4 + 2];
            float4 v3 = Xi4[i * 32 + grp * 4 + 3];
            acc[0]  = fmaf(w, v0.x, acc[0]);  acc[1]  = fmaf(w, v0.y, acc[1]);
            acc[2]  = fmaf(w, v0.z, acc[2]);  acc[3]  = fmaf(w, v0.w, acc[3]);
            acc[4]  = fmaf(w, v1.x, acc[4]);  acc[5]  = fmaf(w, v1.y, acc[5]);
            acc[6]  = fmaf(w, v1.z, acc[6]);  acc[7]  = fmaf(w, v1.w, acc[7]);
            acc[8]  = fmaf(w, v2.x, acc[8]);  acc[9]  = fmaf(w, v2.y, acc[9]);
            acc[10] = fmaf(w, v2.z, acc[10]); acc[11] = fmaf(w, v2.w, acc[11]);
            acc[12] = fmaf(w, v3.x, acc[12]); acc[13] = fmaf(w, v3.y, acc[13]);
            acc[14] = fmaf(w, v3.z, acc[14]); acc[15] = fmaf(w, v3.w, acc[15]);
        }
        __syncthreads();
    }

    red[grp * 32 + jj] = sa;
    __syncthreads();
    if (t < 32) {
        float s2 = 0.0f;
        #pragma unroll
        for (int g = 0; g < 8; g++) s2 += red[g * 32 + t];
        g_saP[sid * NN + jb + t] = s2;
    }
    int j = jb + jj;
    #pragma unroll
    for (int q = 0; q < 16; q++) {
        int p = grp * 16 + q;
        g_muP[((size_t)sid * NN + j) * PP + p] = acc[q];
    }
}

// ---------------- finalize mu; U = x - mu, ||U||^2, <y,U> ----------------
__global__ void k_U(const float* __restrict__ x) {
    int row = blockIdx.x;
    int p   = threadIdx.x;  // 128
    float xv = x[(size_t)row * PP + p];

    float num = 0.0f, den = 0.0f;
    #pragma unroll
    for (int s = 0; s < SPLIT; s++) {
        num += g_muP[((size_t)s * NN + row) * PP + p];
        den += g_saP[s * NN + row];
    }
    float m = (den > 0.0f) ? num / den : xv;   // NaN-guard fallback to y

    float u = xv - m;
    g_U[(size_t)row * PP + p] = u;
    float a = u * u, b = xv * u;
    #pragma unroll
    for (int o = 16; o; o >>= 1) {
        a += __shfl_xor_sync(0xffffffffu, a, o);
        b += __shfl_xor_sync(0xffffffffu, b, o);
    }
    __shared__ float ra[4], rb[4];
    if ((p & 31) == 0) { ra[p >> 5] = a; rb[p >> 5] = b; }
    __syncthreads();
    if (p == 0) {
        g_un2[row] = ra[0] + ra[1] + ra[2] + ra[3];
        g_yU[row]  = rb[0] + rb[1] + rb[2] + rb[3];
    }
}

// ---------------- weight2 ----------------
__device__ __forceinline__ float wfun2(float d, float r) {
    if (d < 0.5f * r) return 1.0f;
    if (d >= r) return 0.0f;
    float tq = (2.0f * d - r) / r;
    float b  = 1.0f - tq * tq;
    return b * b * b;
}

// ---------------- beta pass (partial over i-range) ----------------
__global__ void k_beta(const float* __restrict__ x,
                       const float* __restrict__ r1p,
                       const float* __restrict__ r2p) {
    extern __shared__ float sm[];
    float* Us  = sm;                   // 32*132 (padded rows for conflict-free LDS.128)
    float* Xi  = Us + 32 * 132;        // 64*128
    float* ws  = Xi + 64 * PP;         // 64*33
    float* red = ws + 64 * 33;         // 8*32
    int jb  = blockIdx.x * 32;
    int sid = blockIdx.y;
    int t   = threadIdx.x;
    int jj = t & 31, grp = t >> 5;

    float md  = sqrtf(__int_as_float(g_mdbits));
    float r1e = fminf(__ldg(r1p), md);
    float r2e = fminf(__ldg(r2p), md);

    #pragma unroll
    for (int u = 0; u < 16; u++) {
        int idx = t + u * 256;                   // 0..4095
        int r = idx >> 7, c = idx & 127;
        Us[r * 132 + c] = g_U[(size_t)(jb + r) * PP + c];
    }
    __syncthreads();

    float un2 = g_un2[jb + jj];
    float yu  = g_yU[jb + jj];

    float acc[16];
    #pragma unroll
    for (int q = 0; q < 16; q++) acc[q] = 0.0f;
    float sb = 0.0f;

    const float4* x4g = (const float4*)x;
    const float4* Uv  = (const float4*)(Us + jj * 132);

    int ibeg = sid * CHUNK, iend = ibeg + CHUNK;
    for (int ib = ibeg; ib < iend; ib += 64) {
        #pragma unroll
        for (int u = 0; u < 8; u++) {
            int idx = t + u * 256;
            ((float4*)Xi)[idx] = x4g[ib * 32 + idx];
        }
        __syncthreads();
        const float4* Xi4 = (const float4*)Xi;

        // ps[i][jj] = <x_i, U_jj>
        float ps[8];
        #pragma unroll
        for (int s = 0; s < 8; s++) ps[s] = 0.0f;
        #pragma unroll 4
        for (int k4 = 0; k4 < 32; k4++) {
            float4 u4 = Uv[k4];
            #pragma unroll
            for (int s = 0; s < 8; s++) {
                float4 xv = Xi4[(grp * 8 + s) * 32 + k4];
                ps[s] = fmaf(xv.x, u4.x, fmaf(xv.y, u4.y,
                        fmaf(xv.z, u4.z, fmaf(xv.w, u4.w, ps[s]))));
            }
        }
        // weights
        #pragma unroll
        for (int s = 0; s < 8; s++) {
            int il = grp * 8 + s;
            float d2c = g_d2[(size_t)(ib + il) * NN + jb + jj];
            float psv = ps[s] - yu;
            float du2 = fmaxf(psv * psv * un2, 1e-6f);
            float dv  = sqrtf(fmaxf(d2c - du2, 1e-6f));
            float du  = sqrtf(du2);
            float w   = wfun2(dv, r1e) * wfun2(du, r2e);
            ws[il * 33 + jj] = w;
            sb += w;
        }
        __syncthreads();
        // accumulate eZ
        #pragma unroll 4
        for (int i = 0; i < 64; i++) {
            float w   = ws[i * 33 + jj];
            float4 v0 = Xi4[i * 32 + grp * 4 + 0];
            float4 v1 = Xi4[i * 32 + grp * 4 + 1];
            float4 v2 = Xi4[i * 32 + grp * 4 + 2];
            float4 v3 = Xi4[i * 32 + grp * 4 + 3];
            acc[0]  = fmaf(w, v0.x, acc[0]);  acc[1]  = fmaf(w, v0.y, acc[1]);
            acc[2]  = fmaf(w, v0.z, acc[2]);  acc[3]  = fmaf(w, v0.w, acc[3]);
            acc[4]  = fmaf(w, v1.x, acc[4]);  acc[5]  = fmaf(w, v1.y, acc[5]);
            acc[6]  = fmaf(w, v1.z, acc[6]);  acc[7]  = fmaf(w, v1.w, acc[7]);
            acc[8]  = fmaf(w, v2.x, acc[8]);  acc[9]  = fmaf(w, v2.y, acc[9]);
            acc[10] = fmaf(w, v2.z, acc[10]); acc[11] = fmaf(w, v2.w, acc[11]);
            acc[12] = fmaf(w, v3.x, acc[12]); acc[13] = fmaf(w, v3.y, acc[13]);
            acc[14] = fmaf(w, v3.z, acc[14]); acc[15] = fmaf(w, v3.w, acc[15]);
        }
        __syncthreads();
    }

    red[grp * 32 + jj] = sb;
    __syncthreads();
    if (t < 32) {
        float s2 = 0.0f;
        #pragma unroll
        for (int g = 0; g < 8; g++) s2 += red[g * 32 + t];
        g_sbP[sid * NN + jb + t] = s2;
    }
    int j = jb + jj;
    #pragma unroll
    for (int q = 0; q < 16; q++) {
        int p = grp * 16 + q;
        g_eZP[((size_t)sid * NN + j) * PP + p] = acc[q];
    }
}

// ---------------- fused eZ-finalize + MLP + MSE loss ----------------
__device__ __forceinline__ float gelu_exact(float v) {
    return 0.5f * v * (1.0f + erff(v * 0.70710678118654752f));
}

__global__ void k_mlp(const float* __restrict__ x,
                      const float* __restrict__ We1, const float* __restrict__ be1,
                      const float* __restrict__ We2, const float* __restrict__ be2,
                      const float* __restrict__ Wd1, const float* __restrict__ bd1,
                      const float* __restrict__ Wd2, const float* __restrict__ bd2,
                      float* __restrict__ out) {
    __shared__ float We1s[32 * 129];
    __shared__ float Wd2s[128 * 33];
    __shared__ float We2s[32 * 33];
    __shared__ float Wd1s[32 * 33];
    __shared__ float be1s[32], be2s[32], bd1s[32], bd2s[128];
    int t = threadIdx.x;
    for (int idx = t; idx < 32 * 128; idx += 256)
        We1s[(idx >> 7) * 129 + (idx & 127)] = We1[idx];
    for (int idx = t; idx < 128 * 32; idx += 256)
        Wd2s[(idx >> 5) * 33 + (idx & 31)] = Wd2[idx];
    for (int idx = t; idx < 32 * 32; idx += 256) {
        We2s[(idx >> 5) * 33 + (idx & 31)] = We2[idx];
        Wd1s[(idx >> 5) * 33 + (idx & 31)] = Wd1[idx];
    }
    if (t < 32) { be1s[t] = be1[t]; be2s[t] = be2[t]; bd1s[t] = bd1[t]; }
    if (t < 128) bd2s[t] = bd2[t];
    __syncthreads();

    int lane = t & 31;
    int warp = t >> 5;
    int gw = blockIdx.x * 8 + warp;
    int nw = gridDim.x * 8;
    float part = 0.0f;

    for (int row = gw; row < NN; row += nw) {
        // finalize eZ for this row from the SPLIT partials
        float den = 0.0f;
        #pragma unroll
        for (int s = 0; s < SPLIT; s++) den += g_sbP[s * NN + row];
        float y0 = 0.0f, y1 = 0.0f, y2 = 0.0f, y3 = 0.0f;
        #pragma unroll
        for (int s = 0; s < SPLIT; s++) {
            const float* pr = g_eZP + ((size_t)s * NN + row) * PP;
            y0 += pr[lane];       y1 += pr[32 + lane];
            y2 += pr[64 + lane];  y3 += pr[96 + lane];
        }
        if (den > 0.0f) {
            float inv = 1.0f / den;
            y0 *= inv; y1 *= inv; y2 *= inv; y3 *= inv;
        } else {
            const float* xr = x + (size_t)row * PP;
            y0 = xr[lane];      y1 = xr[32 + lane];
            y2 = xr[64 + lane]; y3 = xr[96 + lane];
        }

        float h = be1s[lane];
        const float* wrow = We1s + lane * 129;
        #pragma unroll 8
        for (int k = 0; k < 32; k++) {
            h = fmaf(__shfl_sync(0xffffffffu, y0, k), wrow[k], h);
            h = fmaf(__shfl_sync(0xffffffffu, y1, k), wrow[32 + k], h);
            h = fmaf(__shfl_sync(0xffffffffu, y2, k), wrow[64 + k], h);
            h = fmaf(__shfl_sync(0xffffffffu, y3, k), wrow[96 + k], h);
        }
        h = gelu_exact(h);

        float z = be2s[lane];
        const float* w2row = We2s + lane * 33;
        #pragma unroll
        for (int m = 0; m < 32; m++)
            z = fmaf(__shfl_sync(0xffffffffu, h, m), w2row[m], z);

        float h2 = bd1s[lane];
        const float* w3row = Wd1s + lane * 33;
        #pragma unroll
        for (int m = 0; m < 32; m++)
            h2 = fmaf(__shfl_sync(0xffffffffu, z, m), w3row[m], h2);
        h2 = gelu_exact(h2);

        float xh[4];
        #pragma unroll
        for (int q = 0; q < 4; q++) xh[q] = bd2s[q * 32 + lane];
        #pragma unroll
        for (int m = 0; m < 32; m++) {
            float hm = __shfl_sync(0xffffffffu, h2, m);
            #pragma unroll
            for (int q = 0; q < 4; q++)
                xh[q] = fmaf(hm, Wd2s[(q * 32 + lane) * 33 + m], xh[q]);
        }
        #pragma unroll
        for (int q = 0; q < 4; q++) {
            int p = q * 32 + lane;
            float s   = 1.0f / (1.0f + expf(-xh[q]));
            float dlt = x[(size_t)row * PP + p] - s;
            part = fmaf(dlt, dlt, part);
        }
    }
    #pragma unroll
    for (int o = 16; o; o >>= 1) part += __shfl_xor_sync(0xffffffffu, part, o);
    if (lane == 0) atomicAdd(out, part * (1.0f / ((float)NN * (float)PP)));
}

// ---------------- launch ----------------
extern "C" void kernel_launch(void* const* d_in, const int* in_sizes, int n_in,
                              void* d_out, int out_size) {
    const float* x   = (const float*)d_in[0];
    const float* r0  = (const float*)d_in[1];
    const float* r1  = (const float*)d_in[2];
    const float* r2  = (const float*)d_in[3];
    const float* We1 = (const float*)d_in[4];
    const float* be1 = (const float*)d_in[5];
    const float* We2 = (const float*)d_in[6];
    const float* be2 = (const float*)d_in[7];
    const float* Wd1 = (const float*)d_in[8];
    const float* bd1 = (const float*)d_in[9];
    const float* Wd2 = (const float*)d_in[10];
    const float* bd2 = (const float*)d_in[11];
    float* out = (float*)d_out;

    size_t smA = (size_t)(64 * PP + 64 * 33 + 8 * 32) * sizeof(float);            // 42240
    size_t smB = (size_t)(32 * 132 + 64 * PP + 64 * 33 + 8 * 32) * sizeof(float); // 59136
    cudaFuncSetAttribute(k_alpha, cudaFuncAttributeMaxDynamicSharedMemorySize, (int)smA);
    cudaFuncSetAttribute(k_beta,  cudaFuncAttributeMaxDynamicSharedMemorySize, (int)smB);

    k_zero<<<1, 1>>>(out);
    k_x2<<<NN, 32>>>(x);
    k_gram<<<dim3(64, 64), 256>>>(x);
    k_alpha<<<dim3(128, SPLIT), 256, smA>>>(x, r0);
    k_U<<<NN, 128>>>(x);
    k_beta<<<dim3(128, SPLIT), 256, smB>>>(x, r1, r2);
    k_mlp<<<128, 256>>>(x, We1, be1, We2, be2, Wd1, bd1, Wd2, bd2, out);
}

// round 4
// speedup vs baseline: 1.5498x; 1.3251x over previous
#include <cuda_runtime.h>
#include <math.h>

#define NN 4096
#define PP 128
#define LL 32
#define ASPLIT 8
#define BSPLIT 4
#define CHA (NN / ASPLIT)   // 512
#define CHB (NN / BSPLIT)   // 1024

// ---------------- scratch (device globals; no allocation) ----------------
__device__ float g_x2[NN];
__device__ float g_d2[(size_t)NN * NN];    // clamped squared distances (64 MB)
__device__ int   g_mdbits;                 // atomicMax of d2c as ordered int
__device__ float g_muP[ASPLIT * NN * PP];  // unnormalized mu partials
__device__ float g_saP[ASPLIT * NN];       // alpha weight-sum partials
__device__ float g_eZP[BSPLIT * NN * PP];  // unnormalized eZ partials
__device__ float g_sbP[BSPLIT * NN];       // beta weight-sum partials
__device__ float g_U[NN * PP];
__device__ float g_un2[NN];
__device__ float g_yU[NN];

// ---------------- f32x2 packed helpers ----------------
typedef unsigned long long ull;

__device__ __forceinline__ void fma2(ull& d, ull a, ull b) {
    asm("fma.rn.f32x2 %0, %1, %2, %0;" : "+l"(d) : "l"(a), "l"(b));
}
__device__ __forceinline__ ull pack2(float lo, float hi) {
    ull r;
    asm("mov.b64 %0, {%1, %2};" : "=l"(r) : "f"(lo), "f"(hi));
    return r;
}
__device__ __forceinline__ float2 unpack2(ull v) {
    float2 r;
    asm("mov.b64 {%0, %1}, %2;" : "=f"(r.x), "=f"(r.y) : "l"(v));
    return r;
}

// ---------------- tiny init ----------------
__global__ void k_zero(float* out) {
    g_mdbits = 0;
    out[0] = 0.0f;
}

// ---------------- x2[i] = ||x_i||^2 ----------------
__global__ void k_x2(const float* __restrict__ x) {
    int row  = blockIdx.x;
    int lane = threadIdx.x;              // 32 threads
    const float4* x4 = (const float4*)x;
    float4 v = x4[row * 32 + lane];
    float s = v.x * v.x + v.y * v.y + v.z * v.z + v.w * v.w;
    #pragma unroll
    for (int o = 16; o; o >>= 1) s += __shfl_xor_sync(0xffffffffu, s, o);
    if (lane == 0) g_x2[row] = s;
}

// ---------------- Gram / dist^2 (128x128 tile, 8x8 per thread, f32x2) ----------------
__global__ __launch_bounds__(256, 2) void k_gram(const float* __restrict__ x) {
    __shared__ float As[8][140];
    __shared__ float Bs[8][140];
    __shared__ float redmax[8];
    int jb = blockIdx.x * 128, ib = blockIdx.y * 128;
    int t  = threadIdx.x;
    int tx = t & 15, ty = t >> 4;        // tx: 8 j's; ty: 8 i's
    ull accP[8][4];
    #pragma unroll
    for (int a = 0; a < 8; a++)
        #pragma unroll
        for (int b = 0; b < 4; b++) accP[a][b] = 0ull;

    int lr = t >> 1, lc = (t & 1) * 4;
    for (int k0 = 0; k0 < PP; k0 += 8) {
        float4 av = *(const float4*)(x + (size_t)(ib + lr) * PP + k0 + lc);
        float4 bv = *(const float4*)(x + (size_t)(jb + lr) * PP + k0 + lc);
        __syncthreads();
        As[lc + 0][lr] = av.x; As[lc + 1][lr] = av.y;
        As[lc + 2][lr] = av.z; As[lc + 3][lr] = av.w;
        Bs[lc + 0][lr] = bv.x; Bs[lc + 1][lr] = bv.y;
        Bs[lc + 2][lr] = bv.z; Bs[lc + 3][lr] = bv.w;
        __syncthreads();
        #pragma unroll
        for (int kk = 0; kk < 8; kk++) {
            float4 a0 = *(const float4*)&As[kk][ty * 8];
            float4 a1 = *(const float4*)&As[kk][ty * 8 + 4];
            float4 b0 = *(const float4*)&Bs[kk][tx * 8];
            float4 b1 = *(const float4*)&Bs[kk][tx * 8 + 4];
            ull bp[4] = { pack2(b0.x, b0.y), pack2(b0.z, b0.w),
                          pack2(b1.x, b1.y), pack2(b1.z, b1.w) };
            float ar[8] = {a0.x, a0.y, a0.z, a0.w, a1.x, a1.y, a1.z, a1.w};
            #pragma unroll
            for (int a = 0; a < 8; a++) {
                ull ap = pack2(ar[a], ar[a]);
                fma2(accP[a][0], ap, bp[0]);
                fma2(accP[a][1], ap, bp[1]);
                fma2(accP[a][2], ap, bp[2]);
                fma2(accP[a][3], ap, bp[3]);
            }
        }
    }

    float xj2[8];
    #pragma unroll
    for (int b = 0; b < 8; b++) xj2[b] = g_x2[jb + tx * 8 + b];

    float lmax = 0.0f;
    #pragma unroll
    for (int a = 0; a < 8; a++) {
        int i = ib + ty * 8 + a;
        float xi2 = g_x2[i];
        float o[8];
        #pragma unroll
        for (int q = 0; q < 4; q++) {
            float2 pr = unpack2(accP[a][q]);
            o[2 * q]     = pr.x;
            o[2 * q + 1] = pr.y;
        }
        float4 s0, s1;
        float* sp0 = &s0.x; float* sp1 = &s1.x;
        #pragma unroll
        for (int b = 0; b < 8; b++) {
            float d2 = xi2 + xj2[b] - 2.0f * o[b];
            d2 = fmaxf(d2, 1e-12f);
            if (b < 4) sp0[b] = d2; else sp1[b - 4] = d2;
            lmax = fmaxf(lmax, d2);
        }
        *(float4*)(g_d2 + (size_t)i * NN + jb + tx * 8)     = s0;
        *(float4*)(g_d2 + (size_t)i * NN + jb + tx * 8 + 4) = s1;
    }
    #pragma unroll
    for (int o = 16; o; o >>= 1)
        lmax = fmaxf(lmax, __shfl_xor_sync(0xffffffffu, lmax, o));
    if ((t & 31) == 0) redmax[t >> 5] = lmax;
    __syncthreads();
    if (t == 0) {
        float m = redmax[0];
        #pragma unroll
        for (int wgi = 1; wgi < 8; wgi++) m = fmaxf(m, redmax[wgi]);
        atomicMax(&g_mdbits, __float_as_int(m));
    }
}

// ---------------- alpha pass (64 j per block, f32x2, partial over i) ----------------
__global__ __launch_bounds__(256, 4) void k_alpha(const float* __restrict__ x,
                                                  const float* __restrict__ r0p) {
    extern __shared__ float sm[];
    float* Xi  = sm;                 // 64*128
    float* ws  = Xi + 64 * PP;       // 64*64
    float* red = ws + 64 * 64;       // 8*64
    int jb  = blockIdx.x * 64;
    int sid = blockIdx.y;
    int t   = threadIdx.x;
    int jj = t & 31, grp = t >> 5;

    float md     = sqrtf(__int_as_float(g_mdbits));
    float r0e    = fminf(__ldg(r0p), md);
    float rr     = r0e * r0e;
    float inv_rr = 1.0f / rr;

    ull accP[2][8];
    #pragma unroll
    for (int h = 0; h < 2; h++)
        #pragma unroll
        for (int q = 0; q < 8; q++) accP[h][q] = 0ull;
    float sa0 = 0.0f, sa1 = 0.0f;

    const float4* x4g = (const float4*)x;
    int ibeg = sid * CHA, iend = ibeg + CHA;
    for (int ib = ibeg; ib < iend; ib += 64) {
        #pragma unroll
        for (int u = 0; u < 8; u++) {
            int idx = t + u * 256;
            ((float4*)Xi)[idx] = x4g[ib * 32 + idx];
        }
        #pragma unroll
        for (int s = 0; s < 8; s++) {
            int il = grp * 8 + s;
            size_t base = (size_t)(ib + il) * NN + jb + jj;
            float d0 = g_d2[base];
            float d1 = g_d2[base + 32];
            float w0 = 0.0f, w1 = 0.0f;
            if (d0 < rr) { float b = 1.0f - d0 * inv_rr; w0 = b * b * b; }
            if (d1 < rr) { float b = 1.0f - d1 * inv_rr; w1 = b * b * b; }
            ws[il * 64 + jj]      = w0;
            ws[il * 64 + 32 + jj] = w1;
            sa0 += w0; sa1 += w1;
        }
        __syncthreads();
        const float4* Xi4 = (const float4*)Xi;
        #pragma unroll 2
        for (int i = 0; i < 64; i++) {
            float w0 = ws[i * 64 + jj];
            float w1 = ws[i * 64 + 32 + jj];
            ull w0p = pack2(w0, w0);
            ull w1p = pack2(w1, w1);
            float4 v0 = Xi4[i * 32 + grp * 4 + 0];
            float4 v1 = Xi4[i * 32 + grp * 4 + 1];
            float4 v2 = Xi4[i * 32 + grp * 4 + 2];
            float4 v3 = Xi4[i * 32 + grp * 4 + 3];
            ull xp[8] = { pack2(v0.x, v0.y), pack2(v0.z, v0.w),
                          pack2(v1.x, v1.y), pack2(v1.z, v1.w),
                          pack2(v2.x, v2.y), pack2(v2.z, v2.w),
                          pack2(v3.x, v3.y), pack2(v3.z, v3.w) };
            #pragma unroll
            for (int q = 0; q < 8; q++) {
                fma2(accP[0][q], w0p, xp[q]);
                fma2(accP[1][q], w1p, xp[q]);
            }
        }
        __syncthreads();
    }

    red[grp * 64 + jj]      = sa0;
    red[grp * 64 + 32 + jj] = sa1;
    __syncthreads();
    if (t < 64) {
        float s2 = 0.0f;
        #pragma unroll
        for (int g = 0; g < 8; g++) s2 += red[g * 64 + t];
        g_saP[sid * NN + jb + t] = s2;
    }
    #pragma unroll
    for (int h = 0; h < 2; h++) {
        int j = jb + h * 32 + jj;
        float* dst = g_muP + ((size_t)sid * NN + j) * PP + grp * 16;
        #pragma unroll
        for (int q = 0; q < 8; q++)
            *(float2*)(dst + 2 * q) = unpack2(accP[h][q]);
    }
}

// ---------------- finalize mu; U = x - mu, ||U||^2, <y,U> ----------------
__global__ void k_U(const float* __restrict__ x) {
    int row = blockIdx.x;
    int p   = threadIdx.x;  // 128
    float xv = x[(size_t)row * PP + p];

    float num = 0.0f, den = 0.0f;
    #pragma unroll
    for (int s = 0; s < ASPLIT; s++) {
        num += g_muP[((size_t)s * NN + row) * PP + p];
        den += g_saP[s * NN + row];
    }
    float m = (den > 0.0f) ? num / den : xv;   // NaN-guard fallback to y

    float u = xv - m;
    g_U[(size_t)row * PP + p] = u;
    float a = u * u, b = xv * u;
    #pragma unroll
    for (int o = 16; o; o >>= 1) {
        a += __shfl_xor_sync(0xffffffffu, a, o);
        b += __shfl_xor_sync(0xffffffffu, b, o);
    }
    __shared__ float ra[4], rb[4];
    if ((p & 31) == 0) { ra[p >> 5] = a; rb[p >> 5] = b; }
    __syncthreads();
    if (p == 0) {
        g_un2[row] = ra[0] + ra[1] + ra[2] + ra[3];
        g_yU[row]  = rb[0] + rb[1] + rb[2] + rb[3];
    }
}

// ---------------- weight2 ----------------
__device__ __forceinline__ float wfun2(float d, float r) {
    if (d < 0.5f * r) return 1.0f;
    if (d >= r) return 0.0f;
    float tq = (2.0f * d - r) / r;
    float b  = 1.0f - tq * tq;
    return b * b * b;
}

// ---------------- beta pass (64 j per block, f32x2, partial over i) ----------------
__global__ __launch_bounds__(256, 2) void k_beta(const float* __restrict__ x,
                                                 const float* __restrict__ r1p,
                                                 const float* __restrict__ r2p) {
    extern __shared__ float sm[];
    float* Us  = sm;                   // 64*136
    float* Xi  = Us + 64 * 136;        // 64*128
    float* ws  = Xi + 64 * PP;         // 64*64
    float* red = ws + 64 * 64;         // 8*64
    int jb  = blockIdx.x * 64;
    int sid = blockIdx.y;
    int t   = threadIdx.x;
    int jj = t & 31, grp = t >> 5;

    float md  = sqrtf(__int_as_float(g_mdbits));
    float r1e = fminf(__ldg(r1p), md);
    float r2e = fminf(__ldg(r2p), md);

    #pragma unroll
    for (int u = 0; u < 32; u++) {
        int idx = t + u * 256;                   // 0..8191
        int r = idx >> 7, c = idx & 127;
        Us[r * 136 + c] = g_U[(size_t)(jb + r) * PP + c];
    }
    __syncthreads();

    float un2_0 = g_un2[jb + jj],      yu0 = g_yU[jb + jj];
    float un2_1 = g_un2[jb + 32 + jj], yu1 = g_yU[jb + 32 + jj];

    ull accP[2][8];
    #pragma unroll
    for (int h = 0; h < 2; h++)
        #pragma unroll
        for (int q = 0; q < 8; q++) accP[h][q] = 0ull;
    float sb0 = 0.0f, sb1 = 0.0f;

    const float4* x4g = (const float4*)x;
    const float4* Uv0 = (const float4*)(Us + jj * 136);
    const float4* Uv1 = (const float4*)(Us + (32 + jj) * 136);

    int ibeg = sid * CHB, iend = ibeg + CHB;
    for (int ib = ibeg; ib < iend; ib += 64) {
        #pragma unroll
        for (int u = 0; u < 8; u++) {
            int idx = t + u * 256;
            ((float4*)Xi)[idx] = x4g[ib * 32 + idx];
        }
        __syncthreads();
        const float4* Xi4 = (const float4*)Xi;

        // ps (k-packed): psP0/1[s] accumulate even/odd-k halves
        ull psP0[8], psP1[8];
        #pragma unroll
        for (int s = 0; s < 8; s++) { psP0[s] = 0ull; psP1[s] = 0ull; }
        #pragma unroll 4
        for (int k4 = 0; k4 < 32; k4++) {
            float4 u0 = Uv0[k4];
            float4 u1 = Uv1[k4];
            ull u0a = pack2(u0.x, u0.y), u0b = pack2(u0.z, u0.w);
            ull u1a = pack2(u1.x, u1.y), u1b = pack2(u1.z, u1.w);
            #pragma unroll
            for (int s = 0; s < 8; s++) {
                float4 xv = Xi4[(grp * 8 + s) * 32 + k4];
                ull xa = pack2(xv.x, xv.y), xb = pack2(xv.z, xv.w);
                fma2(psP0[s], xa, u0a);
                fma2(psP0[s], xb, u0b);
                fma2(psP1[s], xa, u1a);
                fma2(psP1[s], xb, u1b);
            }
        }
        // weights
        #pragma unroll
        for (int s = 0; s < 8; s++) {
            int il = grp * 8 + s;
            size_t base = (size_t)(ib + il) * NN + jb + jj;
            float d0 = g_d2[base];
            float d1 = g_d2[base + 32];
            float2 p0 = unpack2(psP0[s]);
            float2 p1 = unpack2(psP1[s]);
            float psv0 = (p0.x + p0.y) - yu0;
            float psv1 = (p1.x + p1.y) - yu1;
            float du2_0 = fmaxf(psv0 * psv0 * un2_0, 1e-6f);
            float du2_1 = fmaxf(psv1 * psv1 * un2_1, 1e-6f);
            float dv0 = sqrtf(fmaxf(d0 - du2_0, 1e-6f));
            float dv1 = sqrtf(fmaxf(d1 - du2_1, 1e-6f));
            float du0 = sqrtf(du2_0);
            float du1 = sqrtf(du2_1);
            float w0 = wfun2(dv0, r1e) * wfun2(du0, r2e);
            float w1 = wfun2(dv1, r1e) * wfun2(du1, r2e);
            ws[il * 64 + jj]      = w0;
            ws[il * 64 + 32 + jj] = w1;
            sb0 += w0; sb1 += w1;
        }
        __syncthreads();
        // accumulate eZ
        #pragma unroll 2
        for (int i = 0; i < 64; i++) {
            float w0 = ws[i * 64 + jj];
            float w1 = ws[i * 64 + 32 + jj];
            ull w0p = pack2(w0, w0);
            ull w1p = pack2(w1, w1);
            float4 v0 = Xi4[i * 32 + grp * 4 + 0];
            float4 v1 = Xi4[i * 32 + grp * 4 + 1];
            float4 v2 = Xi4[i * 32 + grp * 4 + 2];
            float4 v3 = Xi4[i * 32 + grp * 4 + 3];
            ull xp[8] = { pack2(v0.x, v0.y), pack2(v0.z, v0.w),
                          pack2(v1.x, v1.y), pack2(v1.z, v1.w),
                          pack2(v2.x, v2.y), pack2(v2.z, v2.w),
                          pack2(v3.x, v3.y), pack2(v3.z, v3.w) };
            #pragma unroll
            for (int q = 0; q < 8; q++) {
                fma2(accP[0][q], w0p, xp[q]);
                fma2(accP[1][q], w1p, xp[q]);
            }
        }
        __syncthreads();
    }

    red[grp * 64 + jj]      = sb0;
    red[grp * 64 + 32 + jj] = sb1;
    __syncthreads();
    if (t < 64) {
        float s2 = 0.0f;
        #pragma unroll
        for (int g = 0; g < 8; g++) s2 += red[g * 64 + t];
        g_sbP[sid * NN + jb + t] = s2;
    }
    #pragma unroll
    for (int h = 0; h < 2; h++) {
        int j = jb + h * 32 + jj;
        float* dst = g_eZP + ((size_t)sid * NN + j) * PP + grp * 16;
        #pragma unroll
        for (int q = 0; q < 8; q++)
            *(float2*)(dst + 2 * q) = unpack2(accP[h][q]);
    }
}

// ---------------- fused eZ-finalize + MLP + MSE loss ----------------
__device__ __forceinline__ float gelu_exact(float v) {
    return 0.5f * v * (1.0f + erff(v * 0.70710678118654752f));
}

__global__ void k_mlp(const float* __restrict__ x,
                      const float* __restrict__ We1, const float* __restrict__ be1,
                      const float* __restrict__ We2, const float* __restrict__ be2,
                      const float* __restrict__ Wd1, const float* __restrict__ bd1,
                      const float* __restrict__ Wd2, const float* __restrict__ bd2,
                      float* __restrict__ out) {
    __shared__ float We1s[32 * 129];
    __shared__ float Wd2s[128 * 33];
    __shared__ float We2s[32 * 33];
    __shared__ float Wd1s[32 * 33];
    __shared__ float be1s[32], be2s[32], bd1s[32], bd2s[128];
    int t = threadIdx.x;
    for (int idx = t; idx < 32 * 128; idx += 256)
        We1s[(idx >> 7) * 129 + (idx & 127)] = We1[idx];
    for (int idx = t; idx < 128 * 32; idx += 256)
        Wd2s[(idx >> 5) * 33 + (idx & 31)] = Wd2[idx];
    for (int idx = t; idx < 32 * 32; idx += 256) {
        We2s[(idx >> 5) * 33 + (idx & 31)] = We2[idx];
        Wd1s[(idx >> 5) * 33 + (idx & 31)] = Wd1[idx];
    }
    if (t < 32) { be1s[t] = be1[t]; be2s[t] = be2[t]; bd1s[t] = bd1[t]; }
    if (t < 128) bd2s[t] = bd2[t];
    __syncthreads();

    int lane = t & 31;
    int warp = t >> 5;
    int gw = blockIdx.x * 8 + warp;
    int nw = gridDim.x * 8;
    float part = 0.0f;

    for (int row = gw; row < NN; row += nw) {
        float den = 0.0f;
        #pragma unroll
        for (int s = 0; s < BSPLIT; s++) den += g_sbP[s * NN + row];
        float y0 = 0.0f, y1 = 0.0f, y2 = 0.0f, y3 = 0.0f;
        #pragma unroll
        for (int s = 0; s < BSPLIT; s++) {
            const float* pr = g_eZP + ((size_t)s * NN + row) * PP;
            y0 += pr[lane];       y1 += pr[32 + lane];
            y2 += pr[64 + lane];  y3 += pr[96 + lane];
        }
        if (den > 0.0f) {
            float inv = 1.0f / den;
            y0 *= inv; y1 *= inv; y2 *= inv; y3 *= inv;
        } else {
            const float* xr = x + (size_t)row * PP;
            y0 = xr[lane];      y1 = xr[32 + lane];
            y2 = xr[64 + lane]; y3 = xr[96 + lane];
        }

        float h = be1s[lane];
        const float* wrow = We1s + lane * 129;
        #pragma unroll 8
        for (int k = 0; k < 32; k++) {
            h = fmaf(__shfl_sync(0xffffffffu, y0, k), wrow[k], h);
            h = fmaf(__shfl_sync(0xffffffffu, y1, k), wrow[32 + k], h);
            h = fmaf(__shfl_sync(0xffffffffu, y2, k), wrow[64 + k], h);
            h = fmaf(__shfl_sync(0xffffffffu, y3, k), wrow[96 + k], h);
        }
        h = gelu_exact(h);

        float z = be2s[lane];
        const float* w2row = We2s + lane * 33;
        #pragma unroll
        for (int m = 0; m < 32; m++)
            z = fmaf(__shfl_sync(0xffffffffu, h, m), w2row[m], z);

        float h2 = bd1s[lane];
        const float* w3row = Wd1s + lane * 33;
        #pragma unroll
        for (int m = 0; m < 32; m++)
            h2 = fmaf(__shfl_sync(0xffffffffu, z, m), w3row[m], h2);
        h2 = gelu_exact(h2);

        float xh[4];
        #pragma unroll
        for (int q = 0; q < 4; q++) xh[q] = bd2s[q * 32 + lane];
        #pragma unroll
        for (int m = 0; m < 32; m++) {
            float hm = __shfl_sync(0xffffffffu, h2, m);
            #pragma unroll
            for (int q = 0; q < 4; q++)
                xh[q] = fmaf(hm, Wd2s[(q * 32 + lane) * 33 + m], xh[q]);
        }
        #pragma unroll
        for (int q = 0; q < 4; q++) {
            int p = q * 32 + lane;
            float s   = 1.0f / (1.0f + expf(-xh[q]));
            float dlt = x[(size_t)row * PP + p] - s;
            part = fmaf(dlt, dlt, part);
        }
    }
    #pragma unroll
    for (int o = 16; o; o >>= 1) part += __shfl_xor_sync(0xffffffffu, part, o);
    if (lane == 0) atomicAdd(out, part * (1.0f / ((float)NN * (float)PP)));
}

// ---------------- launch ----------------
extern "C" void kernel_launch(void* const* d_in, const int* in_sizes, int n_in,
                              void* d_out, int out_size) {
    const float* x   = (const float*)d_in[0];
    const float* r0  = (const float*)d_in[1];
    const float* r1  = (const float*)d_in[2];
    const float* r2  = (const float*)d_in[3];
    const float* We1 = (const float*)d_in[4];
    const float* be1 = (const float*)d_in[5];
    const float* We2 = (const float*)d_in[6];
    const float* be2 = (const float*)d_in[7];
    const float* Wd1 = (const float*)d_in[8];
    const float* bd1 = (const float*)d_in[9];
    const float* Wd2 = (const float*)d_in[10];
    const float* bd2 = (const float*)d_in[11];
    float* out = (float*)d_out;

    size_t smA = (size_t)(64 * PP + 64 * 64 + 8 * 64) * sizeof(float);            // 51200
    size_t smB = (size_t)(64 * 136 + 64 * PP + 64 * 64 + 8 * 64) * sizeof(float); // 86016
    cudaFuncSetAttribute(k_alpha, cudaFuncAttributeMaxDynamicSharedMemorySize, (int)smA);
    cudaFuncSetAttribute(k_beta,  cudaFuncAttributeMaxDynamicSharedMemorySize, (int)smB);

    k_zero<<<1, 1>>>(out);
    k_x2<<<NN, 32>>>(x);
    k_gram<<<dim3(32, 32), 256>>>(x);
    k_alpha<<<dim3(64, ASPLIT), 256, smA>>>(x, r0);
    k_U<<<NN, 128>>>(x);
    k_beta<<<dim3(64, BSPLIT), 256, smB>>>(x, r1, r2);
    k_mlp<<<128, 256>>>(x, We1, be1, We2, be2, Wd1, bd1, Wd2, bd2, out);
}